// round 2
// baseline (speedup 1.0000x reference)
#include <cuda_runtime.h>

// SmartDoorClassifierv1 — fully fused SNN forward.
//
// Mathematical reduction: alpha = expf(-200.f) == 0.0f exactly (fp32 underflow),
// so the LIF scan is stateless: spiking LIF == elementwise floor(max(x,0)),
// and the spiking=False readout == identity. The network is a plain CNN:
//   conv1(2ch->8, 2x2, stride2) -> floor(relu) -> maxpool2
//   conv2(8->8, 3x3, pad1)      -> floor(relu) -> maxpool2
//   conv3(8->8, 3x3, pad1)      -> floor(relu) -> maxpool2
//   flatten(512) @ w_fc^T -> (N, 2)
//
// One CTA per sample (N = 1024). All intermediates live in shared memory.

#define THREADS 256

__global__ __launch_bounds__(THREADS)
void snn_fused_kernel(const float* __restrict__ x,
                      const float* __restrict__ w1,
                      const float* __restrict__ w2,
                      const float* __restrict__ w3,
                      const float* __restrict__ wfc,
                      float* __restrict__ out)
{
    __shared__ float sw1[64];            // (8,2,2,2)
    __shared__ float sw2[576];           // (8,8,3,3)
    __shared__ float sw3[576];           // (8,8,3,3)
    __shared__ float p1[8 * 32 * 32];    // pooled stage-1 output
    __shared__ float p2[8 * 16 * 16];    // pooled stage-2 output
    __shared__ float p3[8 * 8 * 8];      // pooled stage-3 output (flatten order)
    __shared__ float red[2][8];          // fc partial sums per warp

    const int tid = threadIdx.x;
    const int n   = blockIdx.x;

    // ---- load weights into smem ----
    if (tid < 64) sw1[tid] = w1[tid];
    for (int i = tid; i < 576; i += THREADS) {
        sw2[i] = w2[i];
        sw3[i] = w3[i];
    }
    __syncthreads();

    // ================= Stage 1: conv1 + floor(relu) + pool2 =================
    // conv1: stride-2 2x2 kernel, no pad -> each pooled output (py,px) depends
    // on a disjoint 4x4 input patch per channel. 1024 positions, 4 per thread.
    const float* xb = x + (size_t)n * (2 * 128 * 128);
    #pragma unroll
    for (int it = 0; it < 4; it++) {
        int pos = tid + it * THREADS;          // 0..1023
        int py = pos >> 5, px = pos & 31;
        float in[2][4][4];
        #pragma unroll
        for (int ic = 0; ic < 2; ic++) {
            const float* src = xb + ic * 16384 + (4 * py) * 128 + 4 * px;
            #pragma unroll
            for (int r = 0; r < 4; r++) {
                float4 v = *reinterpret_cast<const float4*>(src + r * 128);
                in[ic][r][0] = v.x; in[ic][r][1] = v.y;
                in[ic][r][2] = v.z; in[ic][r][3] = v.w;
            }
        }
        #pragma unroll
        for (int oc = 0; oc < 8; oc++) {
            float m = 0.f;
            #pragma unroll
            for (int dy = 0; dy < 2; dy++) {
                #pragma unroll
                for (int dx = 0; dx < 2; dx++) {
                    float acc = 0.f;
                    #pragma unroll
                    for (int ic = 0; ic < 2; ic++) {
                        const float* w = &sw1[(oc * 2 + ic) * 4];
                        acc = fmaf(in[ic][2*dy+0][2*dx+0], w[0], acc);
                        acc = fmaf(in[ic][2*dy+0][2*dx+1], w[1], acc);
                        acc = fmaf(in[ic][2*dy+1][2*dx+0], w[2], acc);
                        acc = fmaf(in[ic][2*dy+1][2*dx+1], w[3], acc);
                    }
                    m = fmaxf(m, floorf(fmaxf(acc, 0.f)));
                }
            }
            p1[oc * 1024 + py * 32 + px] = m;
        }
    }
    __syncthreads();

    // ================= Stage 2: conv2(3x3,p1) + floor(relu) + pool2 =========
    // One pooled (py,px) of 16x16 per thread; 8 oc accumulators x 4 conv pos.
    {
        int py = tid >> 4, px = tid & 15;
        float acc[8][2][2];
        #pragma unroll
        for (int oc = 0; oc < 8; oc++)
            #pragma unroll
            for (int a = 0; a < 2; a++)
                #pragma unroll
                for (int b = 0; b < 2; b++) acc[oc][a][b] = 0.f;

        #pragma unroll
        for (int ic = 0; ic < 8; ic++) {
            float patch[4][4];
            #pragma unroll
            for (int r = 0; r < 4; r++) {
                int y = 2 * py - 1 + r;
                #pragma unroll
                for (int c = 0; c < 4; c++) {
                    int xx = 2 * px - 1 + c;
                    patch[r][c] = (y >= 0 && y < 32 && xx >= 0 && xx < 32)
                                  ? p1[ic * 1024 + y * 32 + xx] : 0.f;
                }
            }
            #pragma unroll
            for (int oc = 0; oc < 8; oc++) {
                const float* w = &sw2[(oc * 8 + ic) * 9];
                #pragma unroll
                for (int dy = 0; dy < 2; dy++) {
                    #pragma unroll
                    for (int dx = 0; dx < 2; dx++) {
                        float a = acc[oc][dy][dx];
                        #pragma unroll
                        for (int ky = 0; ky < 3; ky++)
                            #pragma unroll
                            for (int kx = 0; kx < 3; kx++)
                                a = fmaf(patch[dy+ky][dx+kx], w[ky*3+kx], a);
                        acc[oc][dy][dx] = a;
                    }
                }
            }
        }
        #pragma unroll
        for (int oc = 0; oc < 8; oc++) {
            float m = 0.f;
            #pragma unroll
            for (int dy = 0; dy < 2; dy++)
                #pragma unroll
                for (int dx = 0; dx < 2; dx++)
                    m = fmaxf(m, floorf(fmaxf(acc[oc][dy][dx], 0.f)));
            p2[oc * 256 + py * 16 + px] = m;
        }
    }
    __syncthreads();

    // ================= Stage 3: conv3(3x3,p2) + floor(relu) + pool2 =========
    // 64 pooled positions; 4 threads per position, each handles 2 out-channels.
    {
        int pos = tid >> 2;                // 0..63
        int ocg = tid & 3;                 // -> oc = 2*ocg, 2*ocg+1
        int py = pos >> 3, px = pos & 7;
        float acc[2][2][2];
        #pragma unroll
        for (int j = 0; j < 2; j++)
            #pragma unroll
            for (int a = 0; a < 2; a++)
                #pragma unroll
                for (int b = 0; b < 2; b++) acc[j][a][b] = 0.f;

        #pragma unroll
        for (int ic = 0; ic < 8; ic++) {
            float patch[4][4];
            #pragma unroll
            for (int r = 0; r < 4; r++) {
                int y = 2 * py - 1 + r;
                #pragma unroll
                for (int c = 0; c < 4; c++) {
                    int xx = 2 * px - 1 + c;
                    patch[r][c] = (y >= 0 && y < 16 && xx >= 0 && xx < 16)
                                  ? p2[ic * 256 + y * 16 + xx] : 0.f;
                }
            }
            #pragma unroll
            for (int j = 0; j < 2; j++) {
                int oc = ocg * 2 + j;
                const float* w = &sw3[(oc * 8 + ic) * 9];
                #pragma unroll
                for (int dy = 0; dy < 2; dy++) {
                    #pragma unroll
                    for (int dx = 0; dx < 2; dx++) {
                        float a = acc[j][dy][dx];
                        #pragma unroll
                        for (int ky = 0; ky < 3; ky++)
                            #pragma unroll
                            for (int kx = 0; kx < 3; kx++)
                                a = fmaf(patch[dy+ky][dx+kx], w[ky*3+kx], a);
                        acc[j][dy][dx] = a;
                    }
                }
            }
        }
        #pragma unroll
        for (int j = 0; j < 2; j++) {
            int oc = ocg * 2 + j;
            float m = 0.f;
            #pragma unroll
            for (int dy = 0; dy < 2; dy++)
                #pragma unroll
                for (int dx = 0; dx < 2; dx++)
                    m = fmaxf(m, floorf(fmaxf(acc[j][dy][dx], 0.f)));
            p3[oc * 64 + py * 8 + px] = m;       // flatten order c*64 + y*8 + x
        }
    }
    __syncthreads();

    // ================= Stage 4: fc (512 -> 2) ===============================
    {
        float a0 = 0.f, a1 = 0.f;
        #pragma unroll
        for (int k = 0; k < 2; k++) {
            int j = tid + k * THREADS;           // 0..511
            float v = p3[j];
            a0 = fmaf(v, wfc[j],       a0);
            a1 = fmaf(v, wfc[512 + j], a1);
        }
        #pragma unroll
        for (int off = 16; off > 0; off >>= 1) {
            a0 += __shfl_down_sync(0xffffffffu, a0, off);
            a1 += __shfl_down_sync(0xffffffffu, a1, off);
        }
        if ((tid & 31) == 0) {
            red[0][tid >> 5] = a0;
            red[1][tid >> 5] = a1;
        }
        __syncthreads();
        if (tid == 0) {
            float s0 = 0.f, s1 = 0.f;
            #pragma unroll
            for (int i = 0; i < 8; i++) { s0 += red[0][i]; s1 += red[1][i]; }
            out[n * 2 + 0] = s0;
            out[n * 2 + 1] = s1;
        }
    }
}

extern "C" void kernel_launch(void* const* d_in, const int* in_sizes, int n_in,
                              void* d_out, int out_size)
{
    const float* x   = (const float*)d_in[0];
    const float* w1  = (const float*)d_in[1];
    const float* w2  = (const float*)d_in[2];
    const float* w3  = (const float*)d_in[3];
    const float* wfc = (const float*)d_in[4];
    int nsamples = in_sizes[0] / (2 * 128 * 128);   // 1024
    snn_fused_kernel<<<nsamples, THREADS>>>(x, w1, w2, w3, wfc, (float*)d_out);
}